// round 4
// baseline (speedup 1.0000x reference)
#include <cuda_runtime.h>
#include <cuda_bf16.h>
#include <math.h>

// ---------------------------------------------------------------------------
// VAE_Gumbel: B=4096, D=5000, H=512, Z=64
// Pipeline:
//  1) h  = x @ wc_w1 + b1                      [4096,512]  K=5000
//  2) BN batch stats (biased var) -> scale/shift, apply + ReLU (in place)
//  3) w  = hn @ wc_w2 + b2                     [4096,5000] K=512
//  4) topk fused: w += log(-log(u)); 50-step continuous_topk in registers;
//     xm = x * khot  (overwrites w buffer)
//  5) enc1..enc4 (leaky), mean/logvar GEMMs -> d_out tail
//  6) z = mu + eps*exp(0.5*logvar)
//  7) dec1 (leaky), dec2 (+bias, sigmoid) -> d_out head
// ---------------------------------------------------------------------------

#define Bsz 4096
#define Ddim 5000
#define Hdim 512
#define Zdim 64

__device__ float g_h[Bsz * Hdim];        // h / hn / enc3 out
__device__ float g_w[(size_t)Bsz * Ddim]; // w -> xm
__device__ float g_a[Bsz * 2 * Hdim];    // enc1 out / dec1 out
__device__ float g_b[Bsz * Hdim];        // enc2 out / enc4 out
__device__ float g_z[Bsz * Zdim];
__device__ float g_scale[Hdim];
__device__ float g_shift[Hdim];

// ---------------------------------------------------------------------------
// SGEMM: C[M,N] = A[M,K] @ B[K,N] + bias[N], activation epilogue.
// BM=BN=128, BK=8, 256 threads, 8x8 per-thread tile (split 4+4 with 64 offset
// for conflict-free float4 shared loads). Requirements used here:
//   M % 128 == 0, K % 8 == 0, rows of A and B 16B-aligned. N guarded.
// ---------------------------------------------------------------------------
#define ACT_NONE 0
#define ACT_LEAKY 1
#define ACT_SIGMOID 2

template <int ACT>
__global__ __launch_bounds__(256) void sgemm_kernel(
    const float* __restrict__ A, const float* __restrict__ B,
    const float* __restrict__ bias, float* __restrict__ C,
    int M, int N, int K)
{
    __shared__ float As[8][128];
    __shared__ float Bs[8][128];

    const int tid = threadIdx.x;
    const int tx = tid & 15;   // 0..15
    const int ty = tid >> 4;   // 0..15
    const int m0 = blockIdx.y * 128;
    const int n0 = blockIdx.x * 128;

    // global->shared assignments
    const int a_row = tid >> 1;          // 0..127
    const int a_kk  = (tid & 1) * 4;     // 0 or 4
    const int b_kk  = tid >> 5;          // 0..7
    const int b_col = (tid & 31) * 4;    // 0..124

    float acc[8][8];
#pragma unroll
    for (int i = 0; i < 8; i++)
#pragma unroll
        for (int j = 0; j < 8; j++) acc[i][j] = 0.f;

    const int r0 = ty * 4;
    const int c0 = tx * 4;

    for (int k0 = 0; k0 < K; k0 += 8) {
        // A tile (M edge never hit: M multiple of 128; K multiple of 8)
        float4 av = *(const float4*)(A + (size_t)(m0 + a_row) * K + (k0 + a_kk));
        As[a_kk + 0][a_row] = av.x;
        As[a_kk + 1][a_row] = av.y;
        As[a_kk + 2][a_row] = av.z;
        As[a_kk + 3][a_row] = av.w;

        // B tile (guard N edge)
        {
            int bn = n0 + b_col;
            const float* Bp = B + (size_t)(k0 + b_kk) * N + bn;
            float4 bv;
            if (bn + 3 < N) {
                bv = *(const float4*)Bp;
            } else {
                bv.x = (bn + 0 < N) ? Bp[0] : 0.f;
                bv.y = (bn + 1 < N) ? Bp[1] : 0.f;
                bv.z = (bn + 2 < N) ? Bp[2] : 0.f;
                bv.w = (bn + 3 < N) ? Bp[3] : 0.f;
            }
            *(float4*)&Bs[b_kk][b_col] = bv;
        }
        __syncthreads();

#pragma unroll
        for (int kk = 0; kk < 8; kk++) {
            float4 a0 = *(const float4*)&As[kk][r0];
            float4 a1 = *(const float4*)&As[kk][64 + r0];
            float4 bv0 = *(const float4*)&Bs[kk][c0];
            float4 bv1 = *(const float4*)&Bs[kk][64 + c0];
            float ar[8] = {a0.x, a0.y, a0.z, a0.w, a1.x, a1.y, a1.z, a1.w};
            float br[8] = {bv0.x, bv0.y, bv0.z, bv0.w, bv1.x, bv1.y, bv1.z, bv1.w};
#pragma unroll
            for (int i = 0; i < 8; i++)
#pragma unroll
                for (int j = 0; j < 8; j++)
                    acc[i][j] = fmaf(ar[i], br[j], acc[i][j]);
        }
        __syncthreads();
    }

    // epilogue
#pragma unroll
    for (int ii = 0; ii < 8; ii++) {
        int r = m0 + ((ii < 4) ? (r0 + ii) : (64 + r0 + ii - 4));
#pragma unroll
        for (int jj = 0; jj < 8; jj++) {
            int c = n0 + ((jj < 4) ? (c0 + jj) : (64 + c0 + jj - 4));
            if (c < N) {
                float v = acc[ii][jj] + bias[c];
                if (ACT == ACT_LEAKY)   v = (v > 0.f) ? v : 0.01f * v;
                if (ACT == ACT_SIGMOID) v = 1.f / (1.f + __expf(-v));
                C[(size_t)r * N + c] = v;
            }
        }
    }
}

// ---------------------------------------------------------------------------
// BatchNorm batch statistics (training mode, biased var) -> scale/shift
// grid = H/32 blocks, 256 threads (32 cols x 8 row-groups)
// ---------------------------------------------------------------------------
__global__ void bn_stats_kernel(const float* __restrict__ h,
                                const float* __restrict__ gamma,
                                const float* __restrict__ beta)
{
    const int col = blockIdx.x * 32 + (threadIdx.x & 31);
    const int rg = threadIdx.x >> 5;
    float s = 0.f, s2 = 0.f;
    for (int r = rg; r < Bsz; r += 8) {
        float v = h[(size_t)r * Hdim + col];
        s += v;
        s2 += v * v;
    }
    __shared__ float ss[8][33], sq[8][33];
    ss[rg][threadIdx.x & 31] = s;
    sq[rg][threadIdx.x & 31] = s2;
    __syncthreads();
    if (rg == 0) {
        int c = threadIdx.x & 31;
        float S = 0.f, S2 = 0.f;
#pragma unroll
        for (int i = 0; i < 8; i++) { S += ss[i][c]; S2 += sq[i][c]; }
        float mean = S * (1.f / Bsz);
        float var = S2 * (1.f / Bsz) - mean * mean;
        float rstd = 1.f / sqrtf(var + 1e-5f);
        float sc = gamma[col] * rstd;
        g_scale[col] = sc;
        g_shift[col] = beta[col] - mean * sc;
    }
}

__global__ void bn_apply_kernel(float* __restrict__ h)
{
    int i = blockIdx.x * blockDim.x + threadIdx.x; // 4096*512 total
    float v = h[i];
    int col = i & (Hdim - 1);
    v = fmaf(v, g_scale[col], g_shift[col]);
    h[i] = fmaxf(v, 0.f);
}

// ---------------------------------------------------------------------------
// Fused gumbel + 50-step continuous_topk + xm = x*khot.
// One CTA per row; e[] and khot[] live in registers (20 per thread).
// Identity used: after w += log(m), exp(w/T) = exp(w_old/T) * m^(1/T) = e*m^10.
// Elements suppressed below fp32 range go to exactly 0, matching the
// reference's exp(w/T - huge) -> 0 behavior within tolerance.
// ---------------------------------------------------------------------------
#define TPB 256
#define EPT 20   // 256*20 = 5120 >= 5000

__device__ __forceinline__ float warp_sum(float v) {
#pragma unroll
    for (int o = 16; o; o >>= 1) v += __shfl_xor_sync(0xffffffffu, v, o);
    return v;
}
__device__ __forceinline__ float warp_max(float v) {
#pragma unroll
    for (int o = 16; o; o >>= 1) v = fmaxf(v, __shfl_xor_sync(0xffffffffu, v, o));
    return v;
}

__global__ __launch_bounds__(TPB) void topk_kernel(
    float* __restrict__ w, const float* __restrict__ noise_u,
    const float* __restrict__ x)
{
    __shared__ float sred[8];
    const int row = blockIdx.x;
    const int tid = threadIdx.x;
    const int lane = tid & 31;
    const int wid = tid >> 5;

    float* wr = w + (size_t)row * Ddim;
    const float* ur = noise_u + (size_t)row * Ddim;
    const float* xr = x + (size_t)row * Ddim;

    float e[EPT], kh[EPT];

    // gumbel keys + row max
    float mymax = -INFINITY;
#pragma unroll
    for (int i = 0; i < EPT; i++) {
        int idx = tid + i * TPB;
        float v;
        if (idx < Ddim) {
            float u = ur[idx] + 1e-30f;   // EPSILON clamp as in reference
            v = wr[idx] + logf(-logf(u));
        } else {
            v = -INFINITY;
        }
        e[i] = v;
        mymax = fmaxf(mymax, v);
    }
    // block max
    mymax = warp_max(mymax);
    if (lane == 0) sred[wid] = mymax;
    __syncthreads();
    float bmax = sred[0];
#pragma unroll
    for (int i = 1; i < 8; i++) bmax = fmaxf(bmax, sred[i]);

    // unnormalized exponentials at T = 0.1
#pragma unroll
    for (int i = 0; i < EPT; i++) {
        int idx = tid + i * TPB;
        e[i] = (idx < Ddim) ? __expf((e[i] - bmax) * 10.0f) : 0.f;
        kh[i] = 0.f;
    }

    // 50 selection steps; only math in the loop is FMA/mul + one rcp per step
    for (int step = 0; step < 50; step++) {
        float s = 0.f;
#pragma unroll
        for (int i = 0; i < EPT; i++) s += e[i];
        s = warp_sum(s);
        __syncthreads();                 // protect sred reuse
        if (lane == 0) sred[wid] = s;
        __syncthreads();
        float tot = 0.f;
#pragma unroll
        for (int i = 0; i < 8; i++) tot += sred[i];
        float r = 1.0f / tot;
#pragma unroll
        for (int i = 0; i < EPT; i++) {
            float o = e[i] * r;          // softmax(w/T)
            kh[i] += o;
            float m = fmaxf(1.0f - o, 1e-30f);
            float m2 = m * m;
            float m4 = m2 * m2;
            float m8 = m4 * m4;
            e[i] *= m8 * m2;             // e *= m^10  == exp((w+log m)/T)
        }
    }

    // xm = x * subset (overwrite w buffer)
#pragma unroll
    for (int i = 0; i < EPT; i++) {
        int idx = tid + i * TPB;
        if (idx < Ddim) wr[idx] = xr[idx] * kh[i];
    }
}

// ---------------------------------------------------------------------------
// z = mu + eps * exp(0.5*logvar)
// ---------------------------------------------------------------------------
__global__ void reparam_kernel(const float* __restrict__ mu,
                               const float* __restrict__ lv,
                               const float* __restrict__ eps,
                               float* __restrict__ z)
{
    int i = blockIdx.x * blockDim.x + threadIdx.x; // 4096*64 total
    z[i] = fmaf(eps[i], expf(0.5f * lv[i]), mu[i]);
}

// ---------------------------------------------------------------------------
// launch
// ---------------------------------------------------------------------------
extern "C" void kernel_launch(void* const* d_in, const int* in_sizes, int n_in,
                              void* d_out, int out_size)
{
    const float* x       = (const float*)d_in[0];
    const float* noise_u = (const float*)d_in[1];
    const float* eps     = (const float*)d_in[2];
    const float* wc_w1   = (const float*)d_in[3];
    const float* wc_b1   = (const float*)d_in[4];
    const float* bn_g    = (const float*)d_in[5];
    const float* bn_b    = (const float*)d_in[6];
    const float* wc_w2   = (const float*)d_in[7];
    const float* wc_b2   = (const float*)d_in[8];
    const float* enc_w1  = (const float*)d_in[9];
    const float* enc_b1  = (const float*)d_in[10];
    const float* enc_w2  = (const float*)d_in[11];
    const float* enc_b2  = (const float*)d_in[12];
    const float* enc_w3  = (const float*)d_in[13];
    const float* enc_b3  = (const float*)d_in[14];
    const float* enc_w4  = (const float*)d_in[15];
    const float* enc_b4  = (const float*)d_in[16];
    const float* mean_w  = (const float*)d_in[17];
    const float* mean_b  = (const float*)d_in[18];
    const float* lv_w    = (const float*)d_in[19];
    const float* lv_b    = (const float*)d_in[20];
    const float* dec_w1  = (const float*)d_in[21];
    const float* dec_b1  = (const float*)d_in[22];
    const float* dec_w2  = (const float*)d_in[23];
    const float* dec_b2  = (const float*)d_in[24];

    float *h_, *w_, *a_, *b_, *z_;
    cudaGetSymbolAddress((void**)&h_, g_h);
    cudaGetSymbolAddress((void**)&w_, g_w);
    cudaGetSymbolAddress((void**)&a_, g_a);
    cudaGetSymbolAddress((void**)&b_, g_b);
    cudaGetSymbolAddress((void**)&z_, g_z);

    float* out = (float*)d_out;
    const size_t OFF_MU = (size_t)Bsz * Ddim;            // 20,480,000
    const size_t OFF_LV = OFF_MU + (size_t)Bsz * Zdim;   // 20,742,144

    dim3 blk(256);

    // 1) h = x @ wc_w1 + b1
    sgemm_kernel<ACT_NONE><<<dim3(Hdim / 128, Bsz / 128), blk>>>(
        x, wc_w1, wc_b1, h_, Bsz, Hdim, Ddim);

    // 2) batchnorm (training stats) + relu
    bn_stats_kernel<<<Hdim / 32, 256>>>(h_, bn_g, bn_b);
    bn_apply_kernel<<<(Bsz * Hdim) / 256, 256>>>(h_);

    // 3) w = hn @ wc_w2 + b2
    sgemm_kernel<ACT_NONE><<<dim3((Ddim + 127) / 128, Bsz / 128), blk>>>(
        h_, wc_w2, wc_b2, w_, Bsz, Ddim, Hdim);

    // 4) gumbel + continuous_topk + xm (in place over w)
    topk_kernel<<<Bsz, TPB>>>(w_, noise_u, x);

    // 5) encoder
    sgemm_kernel<ACT_LEAKY><<<dim3(2 * Hdim / 128, Bsz / 128), blk>>>(
        w_, enc_w1, enc_b1, a_, Bsz, 2 * Hdim, Ddim);
    sgemm_kernel<ACT_LEAKY><<<dim3(Hdim / 128, Bsz / 128), blk>>>(
        a_, enc_w2, enc_b2, b_, Bsz, Hdim, 2 * Hdim);
    sgemm_kernel<ACT_LEAKY><<<dim3(Hdim / 128, Bsz / 128), blk>>>(
        b_, enc_w3, enc_b3, h_, Bsz, Hdim, Hdim);
    sgemm_kernel<ACT_LEAKY><<<dim3(Hdim / 128, Bsz / 128), blk>>>(
        h_, enc_w4, enc_b4, b_, Bsz, Hdim, Hdim);

    // mean / logvar straight into d_out tail
    sgemm_kernel<ACT_NONE><<<dim3(1, Bsz / 128), blk>>>(
        b_, mean_w, mean_b, out + OFF_MU, Bsz, Zdim, Hdim);
    sgemm_kernel<ACT_NONE><<<dim3(1, Bsz / 128), blk>>>(
        b_, lv_w, lv_b, out + OFF_LV, Bsz, Zdim, Hdim);

    // 6) reparameterize
    reparam_kernel<<<(Bsz * Zdim) / 256, 256>>>(out + OFF_MU, out + OFF_LV, eps, z_);

    // 7) decoder
    sgemm_kernel<ACT_LEAKY><<<dim3(2 * Hdim / 128, Bsz / 128), blk>>>(
        z_, dec_w1, dec_b1, a_, Bsz, 2 * Hdim, Zdim);
    sgemm_kernel<ACT_SIGMOID><<<dim3((Ddim + 127) / 128, Bsz / 128), blk>>>(
        a_, dec_w2, dec_b2, out, Bsz, Ddim, 2 * Hdim);
}

// round 8
// speedup vs baseline: 2.3071x; 2.3071x over previous
#include <cuda_runtime.h>
#include <cuda_bf16.h>
#include <math.h>
#include <stdint.h>

// ---------------------------------------------------------------------------
// VAE_Gumbel: B=4096, D=5000, H=512, Z=64
// R4: all GEMMs moved to TF32 tensor cores (mma.sync.m16n8k8), rna-rounded
// inputs, double-buffered smem, conflict-free fragment loads.
// ---------------------------------------------------------------------------

#define Bsz 4096
#define Ddim 5000
#define Hdim 512
#define Zdim 64

__device__ float g_h[Bsz * Hdim];         // h / hn / enc3 out
__device__ float g_w[(size_t)Bsz * Ddim]; // w -> xm
__device__ float g_a[Bsz * 2 * Hdim];     // enc1 out / dec1 out
__device__ float g_b[Bsz * Hdim];         // enc2 out / enc4 out
__device__ float g_z[Bsz * Zdim];
__device__ float g_scale[Hdim];
__device__ float g_shift[Hdim];

// round fp32 -> tf32 (round-to-nearest-even on 10-bit mantissa), bits in b32
__device__ __forceinline__ unsigned tf32u(float x) {
    unsigned r;
    asm("cvt.rna.tf32.f32 %0, %1;" : "=r"(r) : "f"(x));
    return r;
}

#define ACT_NONE 0
#define ACT_LEAKY 1
#define ACT_SIGMOID 2

template <int ACT>
__device__ __forceinline__ float act_apply(float v) {
    if (ACT == ACT_LEAKY)   v = (v > 0.f) ? v : 0.01f * v;
    if (ACT == ACT_SIGMOID) v = 1.f / (1.f + __expf(-v));
    return v;
}

// ---------------------------------------------------------------------------
// TF32 tensor-core GEMM: C[M,N] = act(A[M,K] @ B[K,N] + bias[N])
// Block tile 128x128, BK=16, 256 threads = 8 warps (2m x 4n), warp tile 64x32.
// Requirements: M % 128 == 0; rows of A/B 16B-aligned when full tiles in
// range (K*4 and N*4 multiples of 16 here: 5000/512/1024/64 all qualify).
// K and N edges guarded with scalar loads / zero fill.
// ---------------------------------------------------------------------------
template <int ACT>
__global__ __launch_bounds__(256, 2) void tf32_gemm_kernel(
    const float* __restrict__ A, const float* __restrict__ B,
    const float* __restrict__ bias, float* __restrict__ C,
    int M, int N, int K)
{
    // [buf][k][m or n] ; stride 136 -> bank = (8k + x) % 32, conflict-free frags
    __shared__ unsigned As[2][16][136];
    __shared__ unsigned Bs[2][16][136];

    const int tid = threadIdx.x;
    const int lane = tid & 31;
    const int wid = tid >> 5;
    const int wm = (wid & 1) * 64;    // warp row offset in tile
    const int wn = (wid >> 1) * 32;   // warp col offset in tile
    const int m0 = blockIdx.y * 128;
    const int n0 = blockIdx.x * 128;

    // global->smem assignments
    const int a_row = tid >> 1;           // 0..127
    const int a_kc  = (tid & 1) * 8;      // 0 or 8
    const int b_k   = tid >> 4;           // 0..15
    const int b_nc  = (tid & 15) * 8;     // 0..120

    float acc[4][4][4];
#pragma unroll
    for (int i = 0; i < 4; i++)
#pragma unroll
        for (int j = 0; j < 4; j++)
#pragma unroll
            for (int q = 0; q < 4; q++) acc[i][j][q] = 0.f;

    float stA[8], stB[8];
    const int ntile = (K + 15) >> 4;

    auto GLOAD = [&](int k0) {
        const float* Ap = A + (size_t)(m0 + a_row) * K + (k0 + a_kc);
        if (k0 + 16 <= K) {
            float4 v0 = *(const float4*)Ap;
            float4 v1 = *(const float4*)(Ap + 4);
            stA[0] = v0.x; stA[1] = v0.y; stA[2] = v0.z; stA[3] = v0.w;
            stA[4] = v1.x; stA[5] = v1.y; stA[6] = v1.z; stA[7] = v1.w;
        } else {
#pragma unroll
            for (int j = 0; j < 8; j++)
                stA[j] = (k0 + a_kc + j < K) ? Ap[j] : 0.f;
        }
        const float* Bp = B + (size_t)(k0 + b_k) * N + (n0 + b_nc);
        if (k0 + 16 <= K && n0 + 128 <= N) {
            float4 v0 = *(const float4*)Bp;
            float4 v1 = *(const float4*)(Bp + 4);
            stB[0] = v0.x; stB[1] = v0.y; stB[2] = v0.z; stB[3] = v0.w;
            stB[4] = v1.x; stB[5] = v1.y; stB[6] = v1.z; stB[7] = v1.w;
        } else {
            bool kok = (k0 + b_k) < K;
#pragma unroll
            for (int j = 0; j < 8; j++)
                stB[j] = (kok && (n0 + b_nc + j) < N) ? Bp[j] : 0.f;
        }
    };

    auto STS = [&](int buf) {
#pragma unroll
        for (int j = 0; j < 8; j++)
            As[buf][a_kc + j][a_row] = tf32u(stA[j]);
        uint4 u0, u1;
        u0.x = tf32u(stB[0]); u0.y = tf32u(stB[1]); u0.z = tf32u(stB[2]); u0.w = tf32u(stB[3]);
        u1.x = tf32u(stB[4]); u1.y = tf32u(stB[5]); u1.z = tf32u(stB[6]); u1.w = tf32u(stB[7]);
        *(uint4*)&Bs[buf][b_k][b_nc] = u0;
        *(uint4*)&Bs[buf][b_k][b_nc + 4] = u1;
    };

    auto COMPUTE = [&](int buf) {
#pragma unroll
        for (int kk = 0; kk < 2; kk++) {
            const int kb = kk * 8;
            unsigned a[4][4], b[4][2];
            const int ar = lane >> 2;       // 0..7
            const int ac = kb + (lane & 3); // k col
#pragma unroll
            for (int mt = 0; mt < 4; mt++) {
                int r = wm + mt * 16 + ar;
                a[mt][0] = As[buf][ac][r];
                a[mt][1] = As[buf][ac][r + 8];
                a[mt][2] = As[buf][ac + 4][r];
                a[mt][3] = As[buf][ac + 4][r + 8];
            }
#pragma unroll
            for (int nt = 0; nt < 4; nt++) {
                int n = wn + nt * 8 + (lane >> 2);
                b[nt][0] = Bs[buf][kb + (lane & 3)][n];
                b[nt][1] = Bs[buf][kb + 4 + (lane & 3)][n];
            }
#pragma unroll
            for (int mt = 0; mt < 4; mt++)
#pragma unroll
                for (int nt = 0; nt < 4; nt++)
                    asm volatile(
                        "mma.sync.aligned.m16n8k8.row.col.f32.tf32.tf32.f32 "
                        "{%0,%1,%2,%3},{%4,%5,%6,%7},{%8,%9},{%0,%1,%2,%3};\n"
                        : "+f"(acc[mt][nt][0]), "+f"(acc[mt][nt][1]),
                          "+f"(acc[mt][nt][2]), "+f"(acc[mt][nt][3])
                        : "r"(a[mt][0]), "r"(a[mt][1]), "r"(a[mt][2]), "r"(a[mt][3]),
                          "r"(b[nt][0]), "r"(b[nt][1]));
        }
    };

    GLOAD(0);
    STS(0);
    __syncthreads();

    for (int t = 0; t < ntile; t++) {
        if (t + 1 < ntile) GLOAD((t + 1) << 4);
        COMPUTE(t & 1);
        if (t + 1 < ntile) STS((t + 1) & 1);
        __syncthreads();
    }

    // epilogue: c0,c1 at (row, col..col+1), c2,c3 at (row+8, col..col+1)
#pragma unroll
    for (int mt = 0; mt < 4; mt++) {
        int row = m0 + wm + mt * 16 + (lane >> 2);
#pragma unroll
        for (int nt = 0; nt < 4; nt++) {
            int col = n0 + wn + nt * 8 + (lane & 3) * 2;
            if (col + 1 < N) {
                float b0 = bias[col], b1 = bias[col + 1];
                float2 v0, v1;
                v0.x = act_apply<ACT>(acc[mt][nt][0] + b0);
                v0.y = act_apply<ACT>(acc[mt][nt][1] + b1);
                v1.x = act_apply<ACT>(acc[mt][nt][2] + b0);
                v1.y = act_apply<ACT>(acc[mt][nt][3] + b1);
                *(float2*)&C[(size_t)row * N + col] = v0;
                *(float2*)&C[(size_t)(row + 8) * N + col] = v1;
            } else if (col < N) {
                float b0 = bias[col];
                C[(size_t)row * N + col]       = act_apply<ACT>(acc[mt][nt][0] + b0);
                C[(size_t)(row + 8) * N + col] = act_apply<ACT>(acc[mt][nt][2] + b0);
            }
        }
    }
}

// ---------------------------------------------------------------------------
// BatchNorm batch statistics (training mode, biased var) -> scale/shift
// ---------------------------------------------------------------------------
__global__ void bn_stats_kernel(const float* __restrict__ h,
                                const float* __restrict__ gamma,
                                const float* __restrict__ beta)
{
    const int col = blockIdx.x * 32 + (threadIdx.x & 31);
    const int rg = threadIdx.x >> 5;
    float s = 0.f, s2 = 0.f;
    for (int r = rg; r < Bsz; r += 8) {
        float v = h[(size_t)r * Hdim + col];
        s += v;
        s2 += v * v;
    }
    __shared__ float ss[8][33], sq[8][33];
    ss[rg][threadIdx.x & 31] = s;
    sq[rg][threadIdx.x & 31] = s2;
    __syncthreads();
    if (rg == 0) {
        int c = threadIdx.x & 31;
        float S = 0.f, S2 = 0.f;
#pragma unroll
        for (int i = 0; i < 8; i++) { S += ss[i][c]; S2 += sq[i][c]; }
        float mean = S * (1.f / Bsz);
        float var = S2 * (1.f / Bsz) - mean * mean;
        float rstd = 1.f / sqrtf(var + 1e-5f);
        float sc = gamma[col] * rstd;
        g_scale[col] = sc;
        g_shift[col] = beta[col] - mean * sc;
    }
}

__global__ void bn_apply_kernel(float* __restrict__ h)
{
    int i = blockIdx.x * blockDim.x + threadIdx.x;
    float v = h[i];
    int col = i & (Hdim - 1);
    v = fmaf(v, g_scale[col], g_shift[col]);
    h[i] = fmaxf(v, 0.f);
}

// ---------------------------------------------------------------------------
// Fused gumbel + 50-step continuous_topk + xm = x*khot (registers-resident).
// ---------------------------------------------------------------------------
#define TPB 256
#define EPT 20   // 256*20 = 5120 >= 5000

__device__ __forceinline__ float warp_sum(float v) {
#pragma unroll
    for (int o = 16; o; o >>= 1) v += __shfl_xor_sync(0xffffffffu, v, o);
    return v;
}
__device__ __forceinline__ float warp_max(float v) {
#pragma unroll
    for (int o = 16; o; o >>= 1) v = fmaxf(v, __shfl_xor_sync(0xffffffffu, v, o));
    return v;
}

__global__ __launch_bounds__(TPB) void topk_kernel(
    float* __restrict__ w, const float* __restrict__ noise_u,
    const float* __restrict__ x)
{
    __shared__ float sred[8];
    const int row = blockIdx.x;
    const int tid = threadIdx.x;
    const int lane = tid & 31;
    const int wid = tid >> 5;

    float* wr = w + (size_t)row * Ddim;
    const float* ur = noise_u + (size_t)row * Ddim;
    const float* xr = x + (size_t)row * Ddim;

    float e[EPT], kh[EPT];

    float mymax = -INFINITY;
#pragma unroll
    for (int i = 0; i < EPT; i++) {
        int idx = tid + i * TPB;
        float v;
        if (idx < Ddim) {
            float u = ur[idx] + 1e-30f;
            v = wr[idx] + logf(-logf(u));
        } else {
            v = -INFINITY;
        }
        e[i] = v;
        mymax = fmaxf(mymax, v);
    }
    mymax = warp_max(mymax);
    if (lane == 0) sred[wid] = mymax;
    __syncthreads();
    float bmax = sred[0];
#pragma unroll
    for (int i = 1; i < 8; i++) bmax = fmaxf(bmax, sred[i]);

#pragma unroll
    for (int i = 0; i < EPT; i++) {
        int idx = tid + i * TPB;
        e[i] = (idx < Ddim) ? __expf((e[i] - bmax) * 10.0f) : 0.f;
        kh[i] = 0.f;
    }

    for (int step = 0; step < 50; step++) {
        float s = 0.f;
#pragma unroll
        for (int i = 0; i < EPT; i++) s += e[i];
        s = warp_sum(s);
        __syncthreads();
        if (lane == 0) sred[wid] = s;
        __syncthreads();
        float tot = 0.f;
#pragma unroll
        for (int i = 0; i < 8; i++) tot += sred[i];
        float r = 1.0f / tot;
#pragma unroll
        for (int i = 0; i < EPT; i++) {
            float o = e[i] * r;
            kh[i] += o;
            float m = fmaxf(1.0f - o, 1e-30f);
            float m2 = m * m;
            float m4 = m2 * m2;
            float m8 = m4 * m4;
            e[i] *= m8 * m2;   // e *= m^10 == exp((w + log m)/T), T = 0.1
        }
    }

#pragma unroll
    for (int i = 0; i < EPT; i++) {
        int idx = tid + i * TPB;
        if (idx < Ddim) wr[idx] = xr[idx] * kh[i];
    }
}

// ---------------------------------------------------------------------------
// z = mu + eps * exp(0.5*logvar)
// ---------------------------------------------------------------------------
__global__ void reparam_kernel(const float* __restrict__ mu,
                               const float* __restrict__ lv,
                               const float* __restrict__ eps,
                               float* __restrict__ z)
{
    int i = blockIdx.x * blockDim.x + threadIdx.x;
    z[i] = fmaf(eps[i], expf(0.5f * lv[i]), mu[i]);
}

// ---------------------------------------------------------------------------
// launch
// ---------------------------------------------------------------------------
extern "C" void kernel_launch(void* const* d_in, const int* in_sizes, int n_in,
                              void* d_out, int out_size)
{
    const float* x       = (const float*)d_in[0];
    const float* noise_u = (const float*)d_in[1];
    const float* eps     = (const float*)d_in[2];
    const float* wc_w1   = (const float*)d_in[3];
    const float* wc_b1   = (const float*)d_in[4];
    const float* bn_g    = (const float*)d_in[5];
    const float* bn_b    = (const float*)d_in[6];
    const float* wc_w2   = (const float*)d_in[7];
    const float* wc_b2   = (const float*)d_in[8];
    const float* enc_w1  = (const float*)d_in[9];
    const float* enc_b1  = (const float*)d_in[10];
    const float* enc_w2  = (const float*)d_in[11];
    const float* enc_b2  = (const float*)d_in[12];
    const float* enc_w3  = (const float*)d_in[13];
    const float* enc_b3  = (const float*)d_in[14];
    const float* enc_w4  = (const float*)d_in[15];
    const float* enc_b4  = (const float*)d_in[16];
    const float* mean_w  = (const float*)d_in[17];
    const float* mean_b  = (const float*)d_in[18];
    const float* lv_w    = (const float*)d_in[19];
    const float* lv_b    = (const float*)d_in[20];
    const float* dec_w1  = (const float*)d_in[21];
    const float* dec_b1  = (const float*)d_in[22];
    const float* dec_w2  = (const float*)d_in[23];
    const float* dec_b2  = (const float*)d_in[24];

    float *h_, *w_, *a_, *b_, *z_;
    cudaGetSymbolAddress((void**)&h_, g_h);
    cudaGetSymbolAddress((void**)&w_, g_w);
    cudaGetSymbolAddress((void**)&a_, g_a);
    cudaGetSymbolAddress((void**)&b_, g_b);
    cudaGetSymbolAddress((void**)&z_, g_z);

    float* out = (float*)d_out;
    const size_t OFF_MU = (size_t)Bsz * Ddim;
    const size_t OFF_LV = OFF_MU + (size_t)Bsz * Zdim;

    dim3 blk(256);

    // 1) h = x @ wc_w1 + b1         [4096,512] K=5000
    tf32_gemm_kernel<ACT_NONE><<<dim3(Hdim / 128, Bsz / 128), blk>>>(
        x, wc_w1, wc_b1, h_, Bsz, Hdim, Ddim);

    // 2) batchnorm (training stats) + relu
    bn_stats_kernel<<<Hdim / 32, 256>>>(h_, bn_g, bn_b);
    bn_apply_kernel<<<(Bsz * Hdim) / 256, 256>>>(h_);

    // 3) w = hn @ wc_w2 + b2        [4096,5000] K=512
    tf32_gemm_kernel<ACT_NONE><<<dim3((Ddim + 127) / 128, Bsz / 128), blk>>>(
        h_, wc_w2, wc_b2, w_, Bsz, Ddim, Hdim);

    // 4) gumbel + continuous_topk + xm (in place over w)
    topk_kernel<<<Bsz, TPB>>>(w_, noise_u, x);

    // 5) encoder
    tf32_gemm_kernel<ACT_LEAKY><<<dim3(2 * Hdim / 128, Bsz / 128), blk>>>(
        w_, enc_w1, enc_b1, a_, Bsz, 2 * Hdim, Ddim);
    tf32_gemm_kernel<ACT_LEAKY><<<dim3(Hdim / 128, Bsz / 128), blk>>>(
        a_, enc_w2, enc_b2, b_, Bsz, Hdim, 2 * Hdim);
    tf32_gemm_kernel<ACT_LEAKY><<<dim3(Hdim / 128, Bsz / 128), blk>>>(
        b_, enc_w3, enc_b3, h_, Bsz, Hdim, Hdim);
    tf32_gemm_kernel<ACT_LEAKY><<<dim3(Hdim / 128, Bsz / 128), blk>>>(
        h_, enc_w4, enc_b4, b_, Bsz, Hdim, Hdim);

    // mean / logvar straight into d_out tail
    tf32_gemm_kernel<ACT_NONE><<<dim3(1, Bsz / 128), blk>>>(
        b_, mean_w, mean_b, out + OFF_MU, Bsz, Zdim, Hdim);
    tf32_gemm_kernel<ACT_NONE><<<dim3(1, Bsz / 128), blk>>>(
        b_, lv_w, lv_b, out + OFF_LV, Bsz, Zdim, Hdim);

    // 6) reparameterize
    reparam_kernel<<<(Bsz * Zdim) / 256, 256>>>(out + OFF_MU, out + OFF_LV, eps, z_);

    // 7) decoder
    tf32_gemm_kernel<ACT_LEAKY><<<dim3(2 * Hdim / 128, Bsz / 128), blk>>>(
        z_, dec_w1, dec_b1, a_, Bsz, 2 * Hdim, Zdim);
    tf32_gemm_kernel<ACT_SIGMOID><<<dim3((Ddim + 127) / 128, Bsz / 128), blk>>>(
        a_, dec_w2, dec_b2, out, Bsz, Ddim, 2 * Hdim);
}

// round 10
// speedup vs baseline: 2.3132x; 1.0027x over previous
#include <cuda_runtime.h>
#include <cuda_bf16.h>
#include <math.h>
#include <stdint.h>

// ---------------------------------------------------------------------------
// VAE_Gumbel: B=4096, D=5000, H=512, Z=64
// R4: all GEMMs moved to TF32 tensor cores (mma.sync.m16n8k8), rna-rounded
// inputs, double-buffered smem, conflict-free fragment loads.
// ---------------------------------------------------------------------------

#define Bsz 4096
#define Ddim 5000
#define Hdim 512
#define Zdim 64

__device__ float g_h[Bsz * Hdim];         // h / hn / enc3 out
__device__ float g_w[(size_t)Bsz * Ddim]; // w -> xm
__device__ float g_a[Bsz * 2 * Hdim];     // enc1 out / dec1 out
__device__ float g_b[Bsz * Hdim];         // enc2 out / enc4 out
__device__ float g_z[Bsz * Zdim];
__device__ float g_scale[Hdim];
__device__ float g_shift[Hdim];

// round fp32 -> tf32 (round-to-nearest-even on 10-bit mantissa), bits in b32
__device__ __forceinline__ unsigned tf32u(float x) {
    unsigned r;
    asm("cvt.rna.tf32.f32 %0, %1;" : "=r"(r) : "f"(x));
    return r;
}

#define ACT_NONE 0
#define ACT_LEAKY 1
#define ACT_SIGMOID 2

template <int ACT>
__device__ __forceinline__ float act_apply(float v) {
    if (ACT == ACT_LEAKY)   v = (v > 0.f) ? v : 0.01f * v;
    if (ACT == ACT_SIGMOID) v = 1.f / (1.f + __expf(-v));
    return v;
}

// ---------------------------------------------------------------------------
// TF32 tensor-core GEMM: C[M,N] = act(A[M,K] @ B[K,N] + bias[N])
// Block tile 128x128, BK=16, 256 threads = 8 warps (2m x 4n), warp tile 64x32.
// Requirements: M % 128 == 0; rows of A/B 16B-aligned when full tiles in
// range (K*4 and N*4 multiples of 16 here: 5000/512/1024/64 all qualify).
// K and N edges guarded with scalar loads / zero fill.
// ---------------------------------------------------------------------------
template <int ACT>
__global__ __launch_bounds__(256, 2) void tf32_gemm_kernel(
    const float* __restrict__ A, const float* __restrict__ B,
    const float* __restrict__ bias, float* __restrict__ C,
    int M, int N, int K)
{
    // [buf][k][m or n] ; stride 136 -> bank = (8k + x) % 32, conflict-free frags
    __shared__ unsigned As[2][16][136];
    __shared__ unsigned Bs[2][16][136];

    const int tid = threadIdx.x;
    const int lane = tid & 31;
    const int wid = tid >> 5;
    const int wm = (wid & 1) * 64;    // warp row offset in tile
    const int wn = (wid >> 1) * 32;   // warp col offset in tile
    const int m0 = blockIdx.y * 128;
    const int n0 = blockIdx.x * 128;

    // global->smem assignments
    const int a_row = tid >> 1;           // 0..127
    const int a_kc  = (tid & 1) * 8;      // 0 or 8
    const int b_k   = tid >> 4;           // 0..15
    const int b_nc  = (tid & 15) * 8;     // 0..120

    float acc[4][4][4];
#pragma unroll
    for (int i = 0; i < 4; i++)
#pragma unroll
        for (int j = 0; j < 4; j++)
#pragma unroll
            for (int q = 0; q < 4; q++) acc[i][j][q] = 0.f;

    float stA[8], stB[8];
    const int ntile = (K + 15) >> 4;

    auto GLOAD = [&](int k0) {
        const float* Ap = A + (size_t)(m0 + a_row) * K + (k0 + a_kc);
        if (k0 + 16 <= K) {
            float4 v0 = *(const float4*)Ap;
            float4 v1 = *(const float4*)(Ap + 4);
            stA[0] = v0.x; stA[1] = v0.y; stA[2] = v0.z; stA[3] = v0.w;
            stA[4] = v1.x; stA[5] = v1.y; stA[6] = v1.z; stA[7] = v1.w;
        } else {
#pragma unroll
            for (int j = 0; j < 8; j++)
                stA[j] = (k0 + a_kc + j < K) ? Ap[j] : 0.f;
        }
        const float* Bp = B + (size_t)(k0 + b_k) * N + (n0 + b_nc);
        if (k0 + 16 <= K && n0 + 128 <= N) {
            float4 v0 = *(const float4*)Bp;
            float4 v1 = *(const float4*)(Bp + 4);
            stB[0] = v0.x; stB[1] = v0.y; stB[2] = v0.z; stB[3] = v0.w;
            stB[4] = v1.x; stB[5] = v1.y; stB[6] = v1.z; stB[7] = v1.w;
        } else {
            bool kok = (k0 + b_k) < K;
#pragma unroll
            for (int j = 0; j < 8; j++)
                stB[j] = (kok && (n0 + b_nc + j) < N) ? Bp[j] : 0.f;
        }
    };

    auto STS = [&](int buf) {
#pragma unroll
        for (int j = 0; j < 8; j++)
            As[buf][a_kc + j][a_row] = tf32u(stA[j]);
        uint4 u0, u1;
        u0.x = tf32u(stB[0]); u0.y = tf32u(stB[1]); u0.z = tf32u(stB[2]); u0.w = tf32u(stB[3]);
        u1.x = tf32u(stB[4]); u1.y = tf32u(stB[5]); u1.z = tf32u(stB[6]); u1.w = tf32u(stB[7]);
        *(uint4*)&Bs[buf][b_k][b_nc] = u0;
        *(uint4*)&Bs[buf][b_k][b_nc + 4] = u1;
    };

    auto COMPUTE = [&](int buf) {
#pragma unroll
        for (int kk = 0; kk < 2; kk++) {
            const int kb = kk * 8;
            unsigned a[4][4], b[4][2];
            const int ar = lane >> 2;       // 0..7
            const int ac = kb + (lane & 3); // k col
#pragma unroll
            for (int mt = 0; mt < 4; mt++) {
                int r = wm + mt * 16 + ar;
                a[mt][0] = As[buf][ac][r];
                a[mt][1] = As[buf][ac][r + 8];
                a[mt][2] = As[buf][ac + 4][r];
                a[mt][3] = As[buf][ac + 4][r + 8];
            }
#pragma unroll
            for (int nt = 0; nt < 4; nt++) {
                int n = wn + nt * 8 + (lane >> 2);
                b[nt][0] = Bs[buf][kb + (lane & 3)][n];
                b[nt][1] = Bs[buf][kb + 4 + (lane & 3)][n];
            }
#pragma unroll
            for (int mt = 0; mt < 4; mt++)
#pragma unroll
                for (int nt = 0; nt < 4; nt++)
                    asm volatile(
                        "mma.sync.aligned.m16n8k8.row.col.f32.tf32.tf32.f32 "
                        "{%0,%1,%2,%3},{%4,%5,%6,%7},{%8,%9},{%0,%1,%2,%3};\n"
                        : "+f"(acc[mt][nt][0]), "+f"(acc[mt][nt][1]),
                          "+f"(acc[mt][nt][2]), "+f"(acc[mt][nt][3])
                        : "r"(a[mt][0]), "r"(a[mt][1]), "r"(a[mt][2]), "r"(a[mt][3]),
                          "r"(b[nt][0]), "r"(b[nt][1]));
        }
    };

    GLOAD(0);
    STS(0);
    __syncthreads();

    for (int t = 0; t < ntile; t++) {
        if (t + 1 < ntile) GLOAD((t + 1) << 4);
        COMPUTE(t & 1);
        if (t + 1 < ntile) STS((t + 1) & 1);
        __syncthreads();
    }

    // epilogue: c0,c1 at (row, col..col+1), c2,c3 at (row+8, col..col+1)
#pragma unroll
    for (int mt = 0; mt < 4; mt++) {
        int row = m0 + wm + mt * 16 + (lane >> 2);
#pragma unroll
        for (int nt = 0; nt < 4; nt++) {
            int col = n0 + wn + nt * 8 + (lane & 3) * 2;
            if (col + 1 < N) {
                float b0 = bias[col], b1 = bias[col + 1];
                float2 v0, v1;
                v0.x = act_apply<ACT>(acc[mt][nt][0] + b0);
                v0.y = act_apply<ACT>(acc[mt][nt][1] + b1);
                v1.x = act_apply<ACT>(acc[mt][nt][2] + b0);
                v1.y = act_apply<ACT>(acc[mt][nt][3] + b1);
                *(float2*)&C[(size_t)row * N + col] = v0;
                *(float2*)&C[(size_t)(row + 8) * N + col] = v1;
            } else if (col < N) {
                float b0 = bias[col];
                C[(size_t)row * N + col]       = act_apply<ACT>(acc[mt][nt][0] + b0);
                C[(size_t)(row + 8) * N + col] = act_apply<ACT>(acc[mt][nt][2] + b0);
            }
        }
    }
}

// ---------------------------------------------------------------------------
// BatchNorm batch statistics (training mode, biased var) -> scale/shift
// ---------------------------------------------------------------------------
__global__ void bn_stats_kernel(const float* __restrict__ h,
                                const float* __restrict__ gamma,
                                const float* __restrict__ beta)
{
    const int col = blockIdx.x * 32 + (threadIdx.x & 31);
    const int rg = threadIdx.x >> 5;
    float s = 0.f, s2 = 0.f;
    for (int r = rg; r < Bsz; r += 8) {
        float v = h[(size_t)r * Hdim + col];
        s += v;
        s2 += v * v;
    }
    __shared__ float ss[8][33], sq[8][33];
    ss[rg][threadIdx.x & 31] = s;
    sq[rg][threadIdx.x & 31] = s2;
    __syncthreads();
    if (rg == 0) {
        int c = threadIdx.x & 31;
        float S = 0.f, S2 = 0.f;
#pragma unroll
        for (int i = 0; i < 8; i++) { S += ss[i][c]; S2 += sq[i][c]; }
        float mean = S * (1.f / Bsz);
        float var = S2 * (1.f / Bsz) - mean * mean;
        float rstd = 1.f / sqrtf(var + 1e-5f);
        float sc = gamma[col] * rstd;
        g_scale[col] = sc;
        g_shift[col] = beta[col] - mean * sc;
    }
}

__global__ void bn_apply_kernel(float* __restrict__ h)
{
    int i = blockIdx.x * blockDim.x + threadIdx.x;
    float v = h[i];
    int col = i & (Hdim - 1);
    v = fmaf(v, g_scale[col], g_shift[col]);
    h[i] = fmaxf(v, 0.f);
}

// ---------------------------------------------------------------------------
// Fused gumbel + 50-step continuous_topk + xm = x*khot (registers-resident).
// ---------------------------------------------------------------------------
#define TPB 256
#define EPT 20   // 256*20 = 5120 >= 5000

__device__ __forceinline__ float warp_sum(float v) {
#pragma unroll
    for (int o = 16; o; o >>= 1) v += __shfl_xor_sync(0xffffffffu, v, o);
    return v;
}
__device__ __forceinline__ float warp_max(float v) {
#pragma unroll
    for (int o = 16; o; o >>= 1) v = fmaxf(v, __shfl_xor_sync(0xffffffffu, v, o));
    return v;
}

__global__ __launch_bounds__(TPB) void topk_kernel(
    float* __restrict__ w, const float* __restrict__ noise_u,
    const float* __restrict__ x)
{
    __shared__ float sred[8];
    const int row = blockIdx.x;
    const int tid = threadIdx.x;
    const int lane = tid & 31;
    const int wid = tid >> 5;

    float* wr = w + (size_t)row * Ddim;
    const float* ur = noise_u + (size_t)row * Ddim;
    const float* xr = x + (size_t)row * Ddim;

    float e[EPT], kh[EPT];

    float mymax = -INFINITY;
#pragma unroll
    for (int i = 0; i < EPT; i++) {
        int idx = tid + i * TPB;
        float v;
        if (idx < Ddim) {
            float u = ur[idx] + 1e-30f;
            v = wr[idx] + logf(-logf(u));
        } else {
            v = -INFINITY;
        }
        e[i] = v;
        mymax = fmaxf(mymax, v);
    }
    mymax = warp_max(mymax);
    if (lane == 0) sred[wid] = mymax;
    __syncthreads();
    float bmax = sred[0];
#pragma unroll
    for (int i = 1; i < 8; i++) bmax = fmaxf(bmax, sred[i]);

#pragma unroll
    for (int i = 0; i < EPT; i++) {
        int idx = tid + i * TPB;
        e[i] = (idx < Ddim) ? __expf((e[i] - bmax) * 10.0f) : 0.f;
        kh[i] = 0.f;
    }

    for (int step = 0; step < 50; step++) {
        float s = 0.f;
#pragma unroll
        for (int i = 0; i < EPT; i++) s += e[i];
        s = warp_sum(s);
        __syncthreads();
        if (lane == 0) sred[wid] = s;
        __syncthreads();
        float tot = 0.f;
#pragma unroll
        for (int i = 0; i < 8; i++) tot += sred[i];
        float r = 1.0f / tot;
#pragma unroll
        for (int i = 0; i < EPT; i++) {
            float o = e[i] * r;
            kh[i] += o;
            float m = fmaxf(1.0f - o, 1e-30f);
            float m2 = m * m;
            float m4 = m2 * m2;
            float m8 = m4 * m4;
            e[i] *= m8 * m2;   // e *= m^10 == exp((w + log m)/T), T = 0.1
        }
    }

#pragma unroll
    for (int i = 0; i < EPT; i++) {
        int idx = tid + i * TPB;
        if (idx < Ddim) wr[idx] = xr[idx] * kh[i];
    }
}

// ---------------------------------------------------------------------------
// z = mu + eps * exp(0.5*logvar)
// ---------------------------------------------------------------------------
__global__ void reparam_kernel(const float* __restrict__ mu,
                               const float* __restrict__ lv,
                               const float* __restrict__ eps,
                               float* __restrict__ z)
{
    int i = blockIdx.x * blockDim.x + threadIdx.x;
    z[i] = fmaf(eps[i], expf(0.5f * lv[i]), mu[i]);
}

// ---------------------------------------------------------------------------
// launch
// ---------------------------------------------------------------------------
extern "C" void kernel_launch(void* const* d_in, const int* in_sizes, int n_in,
                              void* d_out, int out_size)
{
    const float* x       = (const float*)d_in[0];
    const float* noise_u = (const float*)d_in[1];
    const float* eps     = (const float*)d_in[2];
    const float* wc_w1   = (const float*)d_in[3];
    const float* wc_b1   = (const float*)d_in[4];
    const float* bn_g    = (const float*)d_in[5];
    const float* bn_b    = (const float*)d_in[6];
    const float* wc_w2   = (const float*)d_in[7];
    const float* wc_b2   = (const float*)d_in[8];
    const float* enc_w1  = (const float*)d_in[9];
    const float* enc_b1  = (const float*)d_in[10];
    const float* enc_w2  = (const float*)d_in[11];
    const float* enc_b2  = (const float*)d_in[12];
    const float* enc_w3  = (const float*)d_in[13];
    const float* enc_b3  = (const float*)d_in[14];
    const float* enc_w4  = (const float*)d_in[15];
    const float* enc_b4  = (const float*)d_in[16];
    const float* mean_w  = (const float*)d_in[17];
    const float* mean_b  = (const float*)d_in[18];
    const float* lv_w    = (const float*)d_in[19];
    const float* lv_b    = (const float*)d_in[20];
    const float* dec_w1  = (const float*)d_in[21];
    const float* dec_b1  = (const float*)d_in[22];
    const float* dec_w2  = (const float*)d_in[23];
    const float* dec_b2  = (const float*)d_in[24];

    float *h_, *w_, *a_, *b_, *z_;
    cudaGetSymbolAddress((void**)&h_, g_h);
    cudaGetSymbolAddress((void**)&w_, g_w);
    cudaGetSymbolAddress((void**)&a_, g_a);
    cudaGetSymbolAddress((void**)&b_, g_b);
    cudaGetSymbolAddress((void**)&z_, g_z);

    float* out = (float*)d_out;
    const size_t OFF_MU = (size_t)Bsz * Ddim;
    const size_t OFF_LV = OFF_MU + (size_t)Bsz * Zdim;

    dim3 blk(256);

    // 1) h = x @ wc_w1 + b1         [4096,512] K=5000
    tf32_gemm_kernel<ACT_NONE><<<dim3(Hdim / 128, Bsz / 128), blk>>>(
        x, wc_w1, wc_b1, h_, Bsz, Hdim, Ddim);

    // 2) batchnorm (training stats) + relu
    bn_stats_kernel<<<Hdim / 32, 256>>>(h_, bn_g, bn_b);
    bn_apply_kernel<<<(Bsz * Hdim) / 256, 256>>>(h_);

    // 3) w = hn @ wc_w2 + b2        [4096,5000] K=512
    tf32_gemm_kernel<ACT_NONE><<<dim3((Ddim + 127) / 128, Bsz / 128), blk>>>(
        h_, wc_w2, wc_b2, w_, Bsz, Ddim, Hdim);

    // 4) gumbel + continuous_topk + xm (in place over w)
    topk_kernel<<<Bsz, TPB>>>(w_, noise_u, x);

    // 5) encoder
    tf32_gemm_kernel<ACT_LEAKY><<<dim3(2 * Hdim / 128, Bsz / 128), blk>>>(
        w_, enc_w1, enc_b1, a_, Bsz, 2 * Hdim, Ddim);
    tf32_gemm_kernel<ACT_LEAKY><<<dim3(Hdim / 128, Bsz / 128), blk>>>(
        a_, enc_w2, enc_b2, b_, Bsz, Hdim, 2 * Hdim);
    tf32_gemm_kernel<ACT_LEAKY><<<dim3(Hdim / 128, Bsz / 128), blk>>>(
        b_, enc_w3, enc_b3, h_, Bsz, Hdim, Hdim);
    tf32_gemm_kernel<ACT_LEAKY><<<dim3(Hdim / 128, Bsz / 128), blk>>>(
        h_, enc_w4, enc_b4, b_, Bsz, Hdim, Hdim);

    // mean / logvar straight into d_out tail
    tf32_gemm_kernel<ACT_NONE><<<dim3(1, Bsz / 128), blk>>>(
        b_, mean_w, mean_b, out + OFF_MU, Bsz, Zdim, Hdim);
    tf32_gemm_kernel<ACT_NONE><<<dim3(1, Bsz / 128), blk>>>(
        b_, lv_w, lv_b, out + OFF_LV, Bsz, Zdim, Hdim);

    // 6) reparameterize
    reparam_kernel<<<(Bsz * Zdim) / 256, 256>>>(out + OFF_MU, out + OFF_LV, eps, z_);

    // 7) decoder
    tf32_gemm_kernel<ACT_LEAKY><<<dim3(2 * Hdim / 128, Bsz / 128), blk>>>(
        z_, dec_w1, dec_b1, a_, Bsz, 2 * Hdim, Zdim);
    tf32_gemm_kernel<ACT_SIGMOID><<<dim3((Ddim + 127) / 128, Bsz / 128), blk>>>(
        a_, dec_w2, dec_b2, out, Bsz, Ddim, 2 * Hdim);
}

// round 14
// speedup vs baseline: 2.5855x; 1.1177x over previous
#include <cuda_runtime.h>
#include <cuda_bf16.h>
#include <math.h>
#include <stdint.h>

// ---------------------------------------------------------------------------
// VAE_Gumbel: B=4096, D=5000, H=512, Z=64
// R11: tcgen05 unavailable (toolchain targets compute_103 without 'a').
// mma.sync tf32 GEMMs, restructured:
//   - all GEMM inputs pre-converted to tf32 (u32) by producers
//   - A stored k-paired ((k,k+4) adjacent) -> ld.shared.v2 fragments
//   - cp.async 3-stage pipeline, BK=32, zero-padded K/N scratch (no edges)
//   - mean+logvar merged into one N=128 GEMM
//   - topk: packed f32x2 inner loop, registers-resident
// ---------------------------------------------------------------------------

#define Bsz 4096
#define Ddim 5000
#define Hdim 512
#define Zdim 64
#define KPAD_D 5024          // Ddim padded to 32
#define NPAD_D 5120          // Ddim padded to 128
#define DGRP 628             // KPAD_D / 8

// fp32 scratch
__device__ float g_h[Bsz * Hdim];          // h (pre-BN)
__device__ float g_w[(size_t)Bsz * Ddim];  // w (gumbel input)
__device__ float g_scale[Hdim];
__device__ float g_shift[Hdim];
__device__ float g_mlvb[128];              // packed mean|logvar bias

// tf32 (u32) scratch — zero-initialized at load; pads never written stay 0
__device__ uint32_t g_xt[(size_t)Bsz * KPAD_D];   // x,  k-paired
__device__ uint32_t g_xmt[(size_t)Bsz * KPAD_D];  // xm, k-paired
__device__ uint32_t g_hnt[Bsz * Hdim];            // hn, k-paired
__device__ uint32_t g_e1t[Bsz * 2 * Hdim];        // enc1 out / dec1 out
__device__ uint32_t g_e2t[Bsz * Hdim];
__device__ uint32_t g_e3t[Bsz * Hdim];
__device__ uint32_t g_e4t[Bsz * Hdim];
__device__ uint32_t g_zt[Bsz * Zdim];
// tf32 weights (B operands, plain [Kpad][Npad] layout)
__device__ uint32_t g_w1t[(size_t)KPAD_D * Hdim];
__device__ uint32_t g_w2t[(size_t)Hdim * NPAD_D];
__device__ uint32_t g_ew1t[(size_t)KPAD_D * 2 * Hdim];
__device__ uint32_t g_ew2t[2 * Hdim * Hdim];
__device__ uint32_t g_ew3t[Hdim * Hdim];
__device__ uint32_t g_ew4t[Hdim * Hdim];
__device__ uint32_t g_mlvt[Hdim * 128];
__device__ uint32_t g_dw1t[Zdim * 2 * Hdim];
__device__ uint32_t g_dw2t[(size_t)2 * Hdim * NPAD_D];

__device__ __forceinline__ unsigned tf32u(float x) {
    unsigned r;
    asm("cvt.rna.tf32.f32 %0, %1;" : "=r"(r) : "f"(x));
    return r;
}
__device__ __forceinline__ uint32_t smem_u32(const void* p) {
    uint32_t a;
    asm("{ .reg .u64 t; cvta.to.shared.u64 t, %1; cvt.u32.u64 %0, t; }"
        : "=r"(a) : "l"(p));
    return a;
}
// k-pair permutation within groups of 8: (k,k+4) adjacent
__device__ __forceinline__ int permcol(int c) {
    return (c & ~7) | ((c & 3) * 2) | ((c >> 2) & 1);
}

#define EPI_F32      0
#define EPI_F32_SIG  1
#define EPI_T32_LK   2
#define EPI_MEANLV   3

// ---------------------------------------------------------------------------
// tf32 mma.sync GEMM, pre-converted inputs.
//  At: [M][Kpad] tf32, k-paired per 8-group. Bt: [Kpad][Npad] tf32 plain.
//  Tile 128x128, BK=32, 3-stage cp.async, 8 warps (2m x 4n), warp 64x32.
//  Kpad % 32 == 0, Npad % 128 == 0, M % 128 == 0 (all guaranteed).
// ---------------------------------------------------------------------------
#define A_STAGE   16384                 // 128 rows * 128B
#define B_STRIDE  544                   // bytes per B k-row (136 words)
#define B_STAGE   (32 * B_STRIDE)       // 17408
#define STAGE_BYTES (A_STAGE + B_STAGE) // 33792
#define GEMM_SMEM  (3 * STAGE_BYTES)    // 101376

__device__ __forceinline__ void stage_load(
    uint32_t sb, const uint32_t* __restrict__ At, const uint32_t* __restrict__ Bt,
    int m0, int n0, int k0, int Kpad, int Npad, int tid)
{
    // A: 128 rows x 128B; thread -> row tid>>1, half tid&1 (4 chunks of 16B)
    const int m = tid >> 1, hf = tid & 1;
    const uint32_t* asrc = At + (size_t)(m0 + m) * Kpad + k0;
#pragma unroll
    for (int j = 0; j < 4; j++) {
        int c = hf * 4 + j;
        uint32_t d = sb + m * 128 + ((c ^ ((m & 3) << 1)) << 4);
        asm volatile("cp.async.cg.shared.global [%0], [%1], 16;\n"
                     :: "r"(d), "l"(asrc + c * 4));
    }
    // B: 32 k-rows x 512B (stride 544); thread -> row tid>>3, 4 chunks
    const int r = tid >> 3, cb = tid & 7;
    const uint32_t* bsrc = Bt + (size_t)(k0 + r) * Npad + n0 + cb * 16;
    uint32_t bdst = sb + A_STAGE + r * B_STRIDE + cb * 64;
#pragma unroll
    for (int j = 0; j < 4; j++)
        asm volatile("cp.async.cg.shared.global [%0], [%1], 16;\n"
                     :: "r"(bdst + j * 16), "l"(bsrc + j * 4));
}

template <int EPI>
__global__ __launch_bounds__(256, 2) void tc2_gemm(
    const uint32_t* __restrict__ At, const uint32_t* __restrict__ Bt,
    const float* __restrict__ bias,
    float* __restrict__ C0, float* __restrict__ C1, uint32_t* __restrict__ Ct,
    int M, int N, int Kpad, int Npad)
{
    extern __shared__ char smem[];
    const uint32_t sbase = smem_u32(smem);
    const int tid = threadIdx.x;
    const int lane = tid & 31;
    const int wid = tid >> 5;
    const int wm = (wid & 1) * 64;
    const int wn = (wid >> 1) * 32;
    const int m0 = blockIdx.y * 128;
    const int n0 = blockIdx.x * 128;

    float acc[4][4][4];
#pragma unroll
    for (int i = 0; i < 4; i++)
#pragma unroll
        for (int j = 0; j < 4; j++)
#pragma unroll
            for (int q = 0; q < 4; q++) acc[i][j][q] = 0.f;

    const int nt = Kpad >> 5;

    // prologue: 2 stages (+ empty-group trick keeps wait_group constant)
#pragma unroll
    for (int t = 0; t < 2; t++) {
        if (t < nt) stage_load(sbase + t * STAGE_BYTES, At, Bt, m0, n0, t << 5, Kpad, Npad, tid);
        asm volatile("cp.async.commit_group;\n" ::: "memory");
    }

    const int ar = lane >> 2, ac = lane & 3;

    for (int t = 0; t < nt; t++) {
        asm volatile("cp.async.wait_group 1;\n" ::: "memory");
        __syncthreads();

        const uint32_t as = sbase + (t % 3) * STAGE_BYTES;
        const uint32_t bs = as + A_STAGE;

#pragma unroll
        for (int kk = 0; kk < 4; kk++) {
            uint32_t a[4][4], b[4][2];
#pragma unroll
            for (int mt = 0; mt < 4; mt++) {
                int m = wm + mt * 16 + ar;
                uint32_t ad0 = as + m * 128 +
                    (((kk * 2 + (ac >> 1)) ^ ((m & 3) << 1)) << 4) + (ac & 1) * 8;
                asm("ld.shared.v2.u32 {%0,%1},[%2];"
                    : "=r"(a[mt][0]), "=r"(a[mt][2]) : "r"(ad0));
                int m1 = m + 8;
                uint32_t ad1 = as + m1 * 128 +
                    (((kk * 2 + (ac >> 1)) ^ ((m1 & 3) << 1)) << 4) + (ac & 1) * 8;
                asm("ld.shared.v2.u32 {%0,%1},[%2];"
                    : "=r"(a[mt][1]), "=r"(a[mt][3]) : "r"(ad1));
            }
#pragma unroll
            for (int nn = 0; nn < 4; nn++) {
                int n = wn + nn * 8 + ar;
                asm("ld.shared.u32 %0,[%1];" : "=r"(b[nn][0])
                    : "r"(bs + (kk * 8 + ac) * B_STRIDE + n * 4));
                asm("ld.shared.u32 %0,[%1];" : "=r"(b[nn][1])
                    : "r"(bs + (kk * 8 + 4 + ac) * B_STRIDE + n * 4));
            }
#pragma unroll
            for (int mt = 0; mt < 4; mt++)
#pragma unroll
                for (int nn = 0; nn < 4; nn++)
                    asm volatile(
                        "mma.sync.aligned.m16n8k8.row.col.f32.tf32.tf32.f32 "
                        "{%0,%1,%2,%3},{%4,%5,%6,%7},{%8,%9},{%0,%1,%2,%3};\n"
                        : "+f"(acc[mt][nn][0]), "+f"(acc[mt][nn][1]),
                          "+f"(acc[mt][nn][2]), "+f"(acc[mt][nn][3])
                        : "r"(a[mt][0]), "r"(a[mt][1]), "r"(a[mt][2]), "r"(a[mt][3]),
                          "r"(b[nn][0]), "r"(b[nn][1]));
        }

        if (t + 2 < nt)
            stage_load(sbase + ((t + 2) % 3) * STAGE_BYTES, At, Bt, m0, n0,
                       (t + 2) << 5, Kpad, Npad, tid);
        asm volatile("cp.async.commit_group;\n" ::: "memory");
    }

    // epilogue
#pragma unroll
    for (int mt = 0; mt < 4; mt++) {
        int row = m0 + wm + mt * 16 + (lane >> 2);
#pragma unroll
        for (int nn = 0; nn < 4; nn++) {
            int col = n0 + wn + nn * 8 + (lane & 3) * 2;
            if (EPI == EPI_T32_LK) {
                float b0 = bias[col], b1 = bias[col + 1];
                float v0 = acc[mt][nn][0] + b0, v1 = acc[mt][nn][1] + b1;
                float v2 = acc[mt][nn][2] + b0, v3 = acc[mt][nn][3] + b1;
                v0 = (v0 > 0.f) ? v0 : 0.01f * v0;
                v1 = (v1 > 0.f) ? v1 : 0.01f * v1;
                v2 = (v2 > 0.f) ? v2 : 0.01f * v2;
                v3 = (v3 > 0.f) ? v3 : 0.01f * v3;
                size_t r0 = (size_t)row * Npad, r1 = (size_t)(row + 8) * Npad;
                Ct[r0 + permcol(col)] = tf32u(v0);
                Ct[r0 + permcol(col + 1)] = tf32u(v1);
                Ct[r1 + permcol(col)] = tf32u(v2);
                Ct[r1 + permcol(col + 1)] = tf32u(v3);
            } else if (EPI == EPI_MEANLV) {
                float b0 = g_mlvb[col], b1 = g_mlvb[col + 1];
                float v0 = acc[mt][nn][0] + b0, v1 = acc[mt][nn][1] + b1;
                float v2 = acc[mt][nn][2] + b0, v3 = acc[mt][nn][3] + b1;
                float* d0 = (col < 64) ? C0 : C1;
                int cc = (col < 64) ? col : col - 64;
                d0[(size_t)row * 64 + cc] = v0;
                d0[(size_t)row * 64 + cc + 1] = v1;
                d0[(size_t)(row + 8) * 64 + cc] = v2;
                d0[(size_t)(row + 8) * 64 + cc + 1] = v3;
            } else {
                if (col + 1 < N) {
                    float b0 = bias[col], b1 = bias[col + 1];
                    float v0 = acc[mt][nn][0] + b0, v1 = acc[mt][nn][1] + b1;
                    float v2 = acc[mt][nn][2] + b0, v3 = acc[mt][nn][3] + b1;
                    if (EPI == EPI_F32_SIG) {
                        v0 = 1.f / (1.f + __expf(-v0));
                        v1 = 1.f / (1.f + __expf(-v1));
                        v2 = 1.f / (1.f + __expf(-v2));
                        v3 = 1.f / (1.f + __expf(-v3));
                    }
                    float2 p0; p0.x = v0; p0.y = v1;
                    float2 p1; p1.x = v2; p1.y = v3;
                    *(float2*)&C0[(size_t)row * N + col] = p0;
                    *(float2*)&C0[(size_t)(row + 8) * N + col] = p1;
                } else if (col < N) {
                    float b0 = bias[col];
                    float v0 = acc[mt][nn][0] + b0, v2 = acc[mt][nn][2] + b0;
                    if (EPI == EPI_F32_SIG) {
                        v0 = 1.f / (1.f + __expf(-v0));
                        v2 = 1.f / (1.f + __expf(-v2));
                    }
                    C0[(size_t)row * N + col] = v0;
                    C0[(size_t)(row + 8) * N + col] = v2;
                }
            }
        }
    }
}

// ---------------------------------------------------------------------------
// converters
// ---------------------------------------------------------------------------
__global__ void conv_B_kernel(const float* __restrict__ W, uint32_t* __restrict__ Wt,
                              int K, int N, int Kpad, int Npad)
{
    int i = blockIdx.x * 256 + threadIdx.x;
    if (i >= Kpad * Npad) return;
    int k = i / Npad, n = i - k * Npad;
    float v = (k < K && n < N) ? W[(size_t)k * N + n] : 0.f;
    Wt[i] = tf32u(v);
}

__global__ void conv_mlv_kernel(const float* __restrict__ mw, const float* __restrict__ lw,
                                const float* __restrict__ mb, const float* __restrict__ lb)
{
    int i = blockIdx.x * 256 + threadIdx.x;   // 512*128
    if (i >= Hdim * 128) return;
    int k = i >> 7, n = i & 127;
    float v = (n < 64) ? mw[k * 64 + n] : lw[k * 64 + (n - 64)];
    g_mlvt[i] = tf32u(v);
    if (k == 0) g_mlvb[n] = (n < 64) ? mb[n] : lb[n - 64];
}

__global__ void conv_x_kernel(const float* __restrict__ x, uint32_t* __restrict__ xt)
{
    int g = blockIdx.x * 256 + threadIdx.x;   // Bsz * DGRP groups of 8
    if (g >= Bsz * DGRP) return;
    int m = g / DGRP, gi = g - m * DGRP;
    int k = gi * 8;
    float in[8];
    if (k + 8 <= Ddim) {
        const float* p = x + (size_t)m * Ddim + k;
        float4 v0 = *(const float4*)p;
        float4 v1 = *(const float4*)(p + 4);
        in[0] = v0.x; in[1] = v0.y; in[2] = v0.z; in[3] = v0.w;
        in[4] = v1.x; in[5] = v1.y; in[6] = v1.z; in[7] = v1.w;
    } else {
#pragma unroll
        for (int j = 0; j < 8; j++)
            in[j] = (k + j < Ddim) ? x[(size_t)m * Ddim + k + j] : 0.f;
    }
    uint4 o0, o1;   // out[perm(k&7)] = in[k&7]; perm: 0,2,4,6,1,3,5,7
    o0.x = tf32u(in[0]); o0.z = tf32u(in[1]);
    o1.x = tf32u(in[2]); o1.z = tf32u(in[3]);
    o0.y = tf32u(in[4]); o0.w = tf32u(in[5]);
    o1.y = tf32u(in[6]); o1.w = tf32u(in[7]);
    uint32_t* d = xt + (size_t)m * KPAD_D + k;
    *(uint4*)d = o0;
    *(uint4*)(d + 4) = o1;
}

// ---------------------------------------------------------------------------
// BatchNorm stats + apply(-> tf32 k-paired)
// ---------------------------------------------------------------------------
__global__ void bn_stats_kernel(const float* __restrict__ h,
                                const float* __restrict__ gamma,
                                const float* __restrict__ beta)
{
    const int col = blockIdx.x * 32 + (threadIdx.x & 31);
    const int rg = threadIdx.x >> 5;
    float s = 0.f, s2 = 0.f;
    for (int r = rg; r < Bsz; r += 8) {
        float v = h[(size_t)r * Hdim + col];
        s += v; s2 += v * v;
    }
    __shared__ float ss[8][33], sq[8][33];
    ss[rg][threadIdx.x & 31] = s;
    sq[rg][threadIdx.x & 31] = s2;
    __syncthreads();
    if (rg == 0) {
        int c = threadIdx.x & 31;
        float S = 0.f, S2 = 0.f;
#pragma unroll
        for (int i = 0; i < 8; i++) { S += ss[i][c]; S2 += sq[i][c]; }
        float mean = S * (1.f / Bsz);
        float var = S2 * (1.f / Bsz) - mean * mean;
        float rstd = 1.f / sqrtf(var + 1e-5f);
        float sc = gamma[col] * rstd;
        g_scale[col] = sc;
        g_shift[col] = beta[col] - mean * sc;
    }
}

__global__ void bn_apply_kernel(const float* __restrict__ h, uint32_t* __restrict__ hnt)
{
    int i = blockIdx.x * blockDim.x + threadIdx.x;
    int col = i & (Hdim - 1);
    float v = fmaf(h[i], g_scale[col], g_shift[col]);
    v = fmaxf(v, 0.f);
    hnt[(i & ~(Hdim - 1)) | permcol(col)] = tf32u(v);
}

// ---------------------------------------------------------------------------
// gumbel + 50-step continuous_topk + xm (tf32, k-paired), packed f32x2
// ---------------------------------------------------------------------------
#define TPB 256
#define EPT 20
#define NP  10

typedef unsigned long long u64t;
#define MUL2(o,a,b)   asm("mul.rn.f32x2 %0,%1,%2;"    : "=l"(o) : "l"(a), "l"(b))
#define ADD2(o,a,b)   asm("add.rn.f32x2 %0,%1,%2;"    : "=l"(o) : "l"(a), "l"(b))
#define FMA2(o,a,b,c) asm("fma.rn.f32x2 %0,%1,%2,%3;" : "=l"(o) : "l"(a), "l"(b), "l"(c))
#define PACK2(o,lo,hi)   asm("mov.b64 %0,{%1,%2};" : "=l"(o) : "f"(lo), "f"(hi))
#define UNPACK2(lo,hi,i) asm("mov.b64 {%0,%1},%2;" : "=f"(lo), "=f"(hi) : "l"(i))

__device__ __forceinline__ float warp_sum(float v) {
#pragma unroll
    for (int o = 16; o; o >>= 1) v += __shfl_xor_sync(0xffffffffu, v, o);
    return v;
}
__device__ __forceinline__ float warp_max(float v) {
#pragma unroll
    for (int o = 16; o; o >>= 1) v = fmaxf(v, __shfl_xor_sync(0xffffffffu, v, o));
    return v;
}

__global__ __launch_bounds__(TPB) void topk_kernel(
    const float* __restrict__ w, const float* __restrict__ noise_u,
    const float* __restrict__ x, uint32_t* __restrict__ xmt)
{
    __shared__ float sred[2][8];
    const int row = blockIdx.x;
    const int tid = threadIdx.x;
    const int lane = tid & 31;
    const int wid = tid >> 5;

    const float* wr = w + (size_t)row * Ddim;
    const float* ur = noise_u + (size_t)row * Ddim;
    const float* xr = x + (size_t)row * Ddim;

    float ev[EPT];
    float mymax = -INFINITY;
#pragma unroll
    for (int i = 0; i < EPT; i++) {
        int idx = tid + i * TPB;
        float v;
        if (idx < Ddim) {
            float u = ur[idx] + 1e-30f;
            v = wr[idx] + logf(-logf(u));
        } else v = -INFINITY;
        ev[i] = v;
        mymax = fmaxf(mymax, v);
    }
    mymax = warp_max(mymax);
    if (lane == 0) sred[0][wid] = mymax;
    __syncthreads();
    float bmax = sred[0][0];
#pragma unroll
    for (int i = 1; i < 8; i++) bmax = fmaxf(bmax, sred[0][i]);
    __syncthreads();

    u64t e2[NP], kh2[NP], ONE2, NEG2;
    PACK2(ONE2, 1.0f, 1.0f);
    PACK2(NEG2, -1.0f, -1.0f);
#pragma unroll
    for (int i = 0; i < NP; i++) {
        float a0 = (tid + (2 * i) * TPB < Ddim) ? __expf((ev[2 * i] - bmax) * 10.0f) : 0.f;
        float a1 = (tid + (2 * i + 1) * TPB < Ddim) ? __expf((ev[2 * i + 1] - bmax) * 10.0f) : 0.f;
        PACK2(e2[i], a0, a1);
        PACK2(kh2[i], 0.f, 0.f);
    }

    for (int step = 0; step < 50; step++) {
        u64t acc0 = e2[0], acc1 = e2[1];
#pragma unroll
        for (int i = 2; i < NP; i += 2) {
            ADD2(acc0, acc0, e2[i]);
            ADD2(acc1, acc1, e2[i + 1]);
        }
        ADD2(acc0, acc0, acc1);
        float slo, shi;
        UNPACK2(slo, shi, acc0);
        float s = warp_sum(slo + shi);
        if (lane == 0) sred[step & 1][wid] = s;
        __syncthreads();
        float tot = 0.f;
#pragma unroll
        for (int i = 0; i < 8; i++) tot += sred[step & 1][i];
        float r = 1.0f / fmaxf(tot, 1e-35f);
        u64t rr; PACK2(rr, r, r);
#pragma unroll
        for (int i = 0; i < NP; i++) {
            u64t o, m, m2, m4, m8, m10;
            MUL2(o, e2[i], rr);
            ADD2(kh2[i], kh2[i], o);
            FMA2(m, o, NEG2, ONE2);      // m = 1 - o (exact)
            MUL2(m2, m, m);
            MUL2(m4, m2, m2);
            MUL2(m8, m4, m4);
            MUL2(m10, m8, m2);
            MUL2(e2[i], e2[i], m10);     // e *= m^10 == exp((w + log m)/T)
        }
    }

    uint32_t* xo = xmt + (size_t)row * KPAD_D;
#pragma unroll
    for (int i = 0; i < NP; i++) {
        float k0, k1;
        UNPACK2(k0, k1, kh2[i]);
        int i0 = tid + (2 * i) * TPB;
        int i1 = tid + (2 * i + 1) * TPB;
        if (i0 < Ddim) xo[permcol(i0)] = tf32u(xr[i0] * k0);
        if (i1 < Ddim) xo[permcol(i1)] = tf32u(xr[i1] * k1);
    }
}

// ---------------------------------------------------------------------------
// z = mu + eps*exp(0.5*logvar)  -> tf32 k-paired
// ---------------------------------------------------------------------------
__global__ void reparam_kernel(const float* __restrict__ mu,
                               const float* __restrict__ lv,
                               const float* __restrict__ eps,
                               uint32_t* __restrict__ zt)
{
    int i = blockIdx.x * blockDim.x + threadIdx.x;
    int col = i & 63;
    float zv = fmaf(eps[i], expf(0.5f * lv[i]), mu[i]);
    zt[(i & ~63) | permcol(col)] = tf32u(zv);
}

// ---------------------------------------------------------------------------
// host launch helpers
// ---------------------------------------------------------------------------
template <int EPI>
static void gemm(const uint32_t* At, const uint32_t* Bt, const float* bias,
                 float* C0, float* C1, uint32_t* Ct, int M, int N, int Kpad, int Npad)
{
    static bool done = false;
    if (!done) {
        cudaFuncSetAttribute(tc2_gemm<EPI>,
                             cudaFuncAttributeMaxDynamicSharedMemorySize, GEMM_SMEM);
        done = true;
    }
    dim3 g(Npad / 128, M / 128), b(256);
    tc2_gemm<EPI><<<g, b, GEMM_SMEM>>>(At, Bt, bias, C0, C1, Ct, M, N, Kpad, Npad);
}

static inline int cdiv(int a, int b) { return (a + b - 1) / b; }

extern "C" void kernel_launch(void* const* d_in, const int* in_sizes, int n_in,
                              void* d_out, int out_size)
{
    const float* x       = (const float*)d_in[0];
    const float* noise_u = (const float*)d_in[1];
    const float* eps     = (const float*)d_in[2];
    const float* wc_w1   = (const float*)d_in[3];
    const float* wc_b1   = (const float*)d_in[4];
    const float* bn_g    = (const float*)d_in[5];
    const float* bn_b    = (const float*)d_in[6];
    const float* wc_w2   = (const float*)d_in[7];
    const float* wc_b2   = (const float*)d_in[8];
    const float* enc_w1  = (const float*)d_in[9];
    const float* enc_b1  = (const float*)d_in[10];
    const float* enc_w2  = (const float*)d_in[11];
    const float* enc_b2  = (const float*)d_in[12];
    const float* enc_w3  = (const float*)d_in[13];
    const float* enc_b3  = (const float*)d_in[14];
    const float* enc_w4  = (const float*)d_in[15];
    const float* enc_b4  = (const float*)d_in[16];
    const float* mean_w  = (const float*)d_in[17];
    const float* mean_b  = (const float*)d_in[18];
    const float* lv_w    = (const float*)d_in[19];
    const float* lv_b    = (const float*)d_in[20];
    const float* dec_w1  = (const float*)d_in[21];
    const float* dec_b1  = (const float*)d_in[22];
    const float* dec_w2  = (const float*)d_in[23];
    const float* dec_b2  = (const float*)d_in[24];

    float *h_, *w_;
    uint32_t *xt_, *xmt_, *hnt_, *e1t_, *e2t_, *e3t_, *e4t_, *zt_;
    uint32_t *w1t_, *w2t_, *ew1t_, *ew2t_, *ew3t_, *ew4t_, *mlvt_, *dw1t_, *dw2t_;
    cudaGetSymbolAddress((void**)&h_, g_h);
    cudaGetSymbolAddress((void**)&w_, g_w);
    cudaGetSymbolAddress((void**)&xt_, g_xt);
    cudaGetSymbolAddress((void**)&xmt_, g_xmt);
    cudaGetSymbolAddress((void**)&hnt_, g_hnt);
    cudaGetSymbolAddress((void**)&e1t_, g_e1t);
    cudaGetSymbolAddress((void**)&e2t_, g_e2t);
    cudaGetSymbolAddress((void**)&e3t_, g_e3t);
    cudaGetSymbolAddress((void**)&e4t_, g_e4t);
    cudaGetSymbolAddress((void**)&zt_, g_zt);
    cudaGetSymbolAddress((void**)&w1t_, g_w1t);
    cudaGetSymbolAddress((void**)&w2t_, g_w2t);
    cudaGetSymbolAddress((void**)&ew1t_, g_ew1t);
    cudaGetSymbolAddress((void**)&ew2t_, g_ew2t);
    cudaGetSymbolAddress((void**)&ew3t_, g_ew3t);
    cudaGetSymbolAddress((void**)&ew4t_, g_ew4t);
    cudaGetSymbolAddress((void**)&mlvt_, g_mlvt);
    cudaGetSymbolAddress((void**)&dw1t_, g_dw1t);
    cudaGetSymbolAddress((void**)&dw2t_, g_dw2t);

    float* out = (float*)d_out;
    const size_t OFF_MU = (size_t)Bsz * Ddim;
    const size_t OFF_LV = OFF_MU + (size_t)Bsz * Zdim;
    float* mu_out = out + OFF_MU;
    float* lv_out = out + OFF_LV;

    // ---- weight + input conversions (independent) ----
    conv_B_kernel<<<cdiv(KPAD_D * Hdim, 256), 256>>>(wc_w1, w1t_, Ddim, Hdim, KPAD_D, Hdim);
    conv_B_kernel<<<cdiv(Hdim * NPAD_D, 256), 256>>>(wc_w2, w2t_, Hdim, Ddim, Hdim, NPAD_D);
    conv_B_kernel<<<cdiv(KPAD_D * 2 * Hdim, 256), 256>>>(enc_w1, ew1t_, Ddim, 2 * Hdim, KPAD_D, 2 * Hdim);
    conv_B_kernel<<<cdiv(2 * Hdim * Hdim, 256), 256>>>(enc_w2, ew2t_, 2 * Hdim, Hdim, 2 * Hdim, Hdim);
    conv_B_kernel<<<cdiv(Hdim * Hdim, 256), 256>>>(enc_w3, ew3t_, Hdim, Hdim, Hdim, Hdim);
    conv_B_kernel<<<cdiv(Hdim * Hdim, 256), 256>>>(enc_w4, ew4t_, Hdim, Hdim, Hdim, Hdim);
    conv_mlv_kernel<<<cdiv(Hdim * 128, 256), 256>>>(mean_w, lv_w, mean_b, lv_b);
    conv_B_kernel<<<cdiv(Zdim * 2 * Hdim, 256), 256>>>(dec_w1, dw1t_, Zdim, 2 * Hdim, Zdim, 2 * Hdim);
    conv_B_kernel<<<cdiv(2 * Hdim * NPAD_D, 256), 256>>>(dec_w2, dw2t_, 2 * Hdim, Ddim, 2 * Hdim, NPAD_D);
    conv_x_kernel<<<cdiv(Bsz * DGRP, 256), 256>>>(x, xt_);

    // 1) h = x @ wc_w1 + b1                       [4096,512] K=5024
    gemm<EPI_F32>(xt_, w1t_, wc_b1, h_, nullptr, nullptr, Bsz, Hdim, KPAD_D, Hdim);

    // 2) batchnorm stats + apply(+relu) -> hn tf32
    bn_stats_kernel<<<Hdim / 32, 256>>>(h_, bn_g, bn_b);
    bn_apply_kernel<<<(Bsz * Hdim) / 256, 256>>>(h_, hnt_);

    // 3) w = hn @ wc_w2 + b2                      [4096,5000] K=512
    gemm<EPI_F32>(hnt_, w2t_, wc_b2, w_, nullptr, nullptr, Bsz, Ddim, Hdim, NPAD_D);

    // 4) gumbel + continuous_topk + xm (tf32)
    topk_kernel<<<Bsz, TPB>>>(w_, noise_u, x, xmt_);

    // 5) encoder (tf32-only outputs)
    gemm<EPI_T32_LK>(xmt_, ew1t_, enc_b1, nullptr, nullptr, e1t_, Bsz, 2 * Hdim, KPAD_D, 2 * Hdim);
    gemm<EPI_T32_LK>(e1t_, ew2t_, enc_b2, nullptr, nullptr, e2t_, Bsz, Hdim, 2 * Hdim, Hdim);
    gemm<EPI_T32_LK>(e2t_, ew3t_, enc_b3, nullptr, nullptr, e3t_, Bsz, Hdim, Hdim, Hdim);
    gemm<EPI_T32_LK>(e3t_, ew4t_, enc_b4, nullptr, nullptr, e4t_, Bsz, Hdim, Hdim, Hdim);

    // mean|logvar merged, N=128 -> d_out tail
    gemm<EPI_MEANLV>(e4t_, mlvt_, nullptr, mu_out, lv_out, nullptr, Bsz, 128, Hdim, 128);

    // 6) reparameterize -> z tf32
    reparam_kernel<<<(Bsz * Zdim) / 256, 256>>>(mu_out, lv_out, eps, zt_);

    // 7) decoder
    gemm<EPI_T32_LK>(zt_, dw1t_, dec_b1, nullptr, nullptr, e1t_, Bsz, 2 * Hdim, Zdim, 2 * Hdim);
    gemm<EPI_F32_SIG>(e1t_, dw2t_, dec_b2, out, nullptr, nullptr, Bsz, Ddim, 2 * Hdim, NPAD_D);
}